// round 2
// baseline (speedup 1.0000x reference)
#include <cuda_runtime.h>
#include <math.h>

#define D       128
#define PTS     64
#define TH      256
#define NTRAIN  32768
#define NB      4096

// shared-memory float offsets
#define OFF_B    16384          // per-layer bias (128)
#define OFF_W4   16512          // final weights 128x4
#define OFF_B4   17024          // final bias (4)
#define OFF_TRK  17040          // track buffers start
#define TRK_SZ   (D*PTS)        // 8192 floats per track
#define SM_MAIN  ((OFF_TRK + 5*TRK_SZ)*4)   // 232000 B
#define SM_BND   ((OFF_TRK + 1*TRK_SZ)*4)   // 100928 B

// scratch (static device globals — no allocations)
__device__ float g_mu[NTRAIN];
__device__ float g_phys[NTRAIN/PTS];     // 512
__device__ float g_mu2[NTRAIN/256];      // 128
__device__ float g_bnd[4*(NB/PTS)];      // 256

// ---------------------------------------------------------------------------
// 64x128 GEMM tile: acc[p][j] += sum_k src[k][p] * W[k][j]
// src k-major (src[k*64+p]); thread tile = 4 points x 8 cols.
// ---------------------------------------------------------------------------
__device__ __forceinline__ void gemm_tile(const float* __restrict__ src,
                                          const float* __restrict__ w,
                                          int pg, int jg, float acc[4][8])
{
    const float4* ap = reinterpret_cast<const float4*>(src) + pg;
    const float*  wp = w + jg;
#pragma unroll 4
    for (int k = 0; k < D; ++k) {
        float4 a4 = ap[k*16];
        const float* wk = wp + k*D;
#pragma unroll
        for (int jj = 0; jj < 8; ++jj) {
            float ww = wk[jj*16];
            acc[0][jj] = fmaf(a4.x, ww, acc[0][jj]);
            acc[1][jj] = fmaf(a4.y, ww, acc[1][jj]);
            acc[2][jj] = fmaf(a4.z, ww, acc[2][jj]);
            acc[3][jj] = fmaf(a4.w, ww, acc[3][jj]);
        }
    }
}

__device__ __forceinline__ void zero_acc(float acc[4][8])
{
#pragma unroll
    for (int jj = 0; jj < 8; ++jj)
#pragma unroll
        for (int i = 0; i < 4; ++i) acc[i][jj] = 0.f;
}

__device__ __forceinline__ void store_tile(float* dst, int pg, int jg,
                                           const float acc[4][8])
{
#pragma unroll
    for (int jj = 0; jj < 8; ++jj) {
        int j = jg + 16*jj;
        *reinterpret_cast<float4*>(dst + j*PTS + pg*4) =
            make_float4(acc[0][jj], acc[1][jj], acc[2][jj], acc[3][jj]);
    }
}

__device__ __forceinline__ void load_weights(float* sm, const float* __restrict__ Wg,
                                             const float* __restrict__ bg, int tid)
{
    float4* dw = reinterpret_cast<float4*>(sm);
    const float4* sw = reinterpret_cast<const float4*>(Wg);
#pragma unroll
    for (int i = 0; i < 16; ++i) dw[tid + i*TH] = sw[tid + i*TH];
    if (tid < 32)
        reinterpret_cast<float4*>(sm + OFF_B)[tid] =
            reinterpret_cast<const float4*>(bg)[tid];
}

// process one derivative track through a tanh layer.
// first-derivative (second=false): z' kept in zs, a' = s*z'
// second-derivative (second=true):  a'' = s*(z'' - 2 a z'^2) using zs
__device__ __forceinline__ void deriv_track(float* trk, const float* sA,
                                            const float* sW, int pg, int jg,
                                            bool second, float zs[4][8])
{
    float acc[4][8];
    zero_acc(acc);
    gemm_tile(trk, sW, pg, jg, acc);
#pragma unroll
    for (int jj = 0; jj < 8; ++jj) {
        float4 av = *reinterpret_cast<const float4*>(sA + (jg + 16*jj)*PTS + pg*4);
        float aa[4] = {av.x, av.y, av.z, av.w};
#pragma unroll
        for (int i = 0; i < 4; ++i) {
            float a = aa[i], s = 1.f - a*a;
            if (!second) {
                float z = acc[i][jj];
                zs[i][jj]  = z;
                acc[i][jj] = s*z;
            } else {
                float z = zs[i][jj];
                acc[i][jj] = s * (acc[i][jj] - 2.f*a*z*z);
            }
        }
    }
    __syncthreads();
    store_tile(trk, pg, jg, acc);
}

// ---------------------------------------------------------------------------
// Main physics kernel: 5-track propagation + Euler residuals. 64 pts/block.
// ---------------------------------------------------------------------------
__global__ void __launch_bounds__(TH, 1)
pinn_main_kernel(const float* __restrict__ x_train,
                 const float* __restrict__ W0, const float* __restrict__ b0,
                 const float* __restrict__ W1, const float* __restrict__ b1,
                 const float* __restrict__ W2, const float* __restrict__ b2,
                 const float* __restrict__ W3, const float* __restrict__ b3,
                 const float* __restrict__ W4, const float* __restrict__ b4)
{
    extern __shared__ float sm[];
    const int tid = threadIdx.x;
    const int jg  = tid & 15;
    const int pg  = tid >> 4;
    const int p0  = blockIdx.x * PTS;

    float* sW   = sm;
    float* sA   = sm + OFF_TRK;
    float* sAx  = sA   + TRK_SZ;
    float* sAy  = sAx  + TRK_SZ;
    float* sAxx = sAy  + TRK_SZ;
    float* sAyy = sAxx + TRK_SZ;

    // final layer weights (persist whole kernel)
    for (int i = tid; i < 512; i += TH) sm[OFF_W4 + i] = W4[i];
    if (tid < 4) sm[OFF_B4 + tid] = b4[tid];

    // ---- input layer (2 -> 128), closed form for all 5 tracks ----
    {
        float xs[4], ys[4];
#pragma unroll
        for (int i = 0; i < 4; ++i) {
            float2 c = reinterpret_cast<const float2*>(x_train)[p0 + pg*4 + i];
            xs[i] = c.x; ys[i] = c.y;
        }
#pragma unroll
        for (int jj = 0; jj < 8; ++jj) {
            int j = jg + 16*jj;
            float w0 = __ldg(W0 + j), w1 = __ldg(W0 + D + j), bb = __ldg(b0 + j);
#pragma unroll
            for (int i = 0; i < 4; ++i) {
                float z = fmaf(xs[i], w0, fmaf(ys[i], w1, bb));
                float a = tanhf(z);
                float s = 1.f - a*a;
                int idx = j*PTS + pg*4 + i;
                sA[idx]  = a;
                sAx[idx] = s*w0;
                sAy[idx] = s*w1;
                float c2 = -2.f*a*s;
                sAxx[idx] = c2*w0*w0;
                sAyy[idx] = c2*w1*w1;
            }
        }
    }

    const float* Wl[3] = {W1, W2, W3};
    const float* bl[3] = {b1, b2, b3};

    for (int l = 0; l < 3; ++l) {
        __syncthreads();
        load_weights(sm, Wl[l], bl[l], tid);
        __syncthreads();

        // value track: a = tanh(A W + b)
        float acc[4][8];
#pragma unroll
        for (int jj = 0; jj < 8; ++jj) {
            float bb = sm[OFF_B + jg + 16*jj];
#pragma unroll
            for (int i = 0; i < 4; ++i) acc[i][jj] = bb;
        }
        gemm_tile(sA, sW, pg, jg, acc);
#pragma unroll
        for (int jj = 0; jj < 8; ++jj)
#pragma unroll
            for (int i = 0; i < 4; ++i) acc[i][jj] = tanhf(acc[i][jj]);
        __syncthreads();
        store_tile(sA, pg, jg, acc);
        __syncthreads();                // new a visible to deriv epilogues

        float zs[4][8];
        deriv_track(sAx,  sA, sW, pg, jg, false, zs);
        deriv_track(sAxx, sA, sW, pg, jg, true,  zs);
        deriv_track(sAy,  sA, sW, pg, jg, false, zs);
        deriv_track(sAyy, sA, sW, pg, jg, true,  zs);
    }
    __syncthreads();

    // ---- final layer (128 -> 4) for all 5 tracks ----
    const int p = tid & 63;
    const int q = tid >> 6;
    float val[5];
#pragma unroll
    for (int t = 0; t < 5; ++t) {
        const float* trk = sA + t*TRK_SZ;
        float d = (t == 0) ? sm[OFF_B4 + q] : 0.f;
#pragma unroll 8
        for (int k = 0; k < D; ++k)
            d = fmaf(trk[k*PTS + p], sm[OFF_W4 + k*4 + q], d);
        val[t] = d;
    }
#pragma unroll
    for (int t = 0; t < 5; ++t) sm[(t*4 + q)*64 + p] = val[t];   // vsm in dead sW area
    __syncthreads();

    // ---- Euler flux residual, one thread per point ----
    float c = 0.f;
    if (tid < 64) {
        float v[5][4];
#pragma unroll
        for (int t = 0; t < 5; ++t)
#pragma unroll
            for (int qq = 0; qq < 4; ++qq)
                v[t][qq] = sm[(t*4 + qq)*64 + tid];

        float rho = v[0][0], P  = v[0][1], u  = v[0][2], w  = v[0][3];
        float rx  = v[1][0], Px = v[1][1], ux = v[1][2], wx = v[1][3];
        float ry  = v[2][0], Py = v[2][1], uy = v[2][2], wy = v[2][3];
        float rxx = v[3][0], Pxx= v[3][1], uxx= v[3][2], wxx= v[3][3];
        float ryy = v[4][0], Pyy= v[4][1], uyy= v[4][2], wyy= v[4][3];

        const float ig = 2.5f;                 // 1/(gamma-1)
        float q2  = u*u + w*w;
        float kx  = u*ux + w*wx;
        float ky  = u*uy + w*wy;
        float E   = P*ig  + 0.5f*rho*q2;
        float Ex  = Px*ig + 0.5f*rx*q2 + rho*kx;
        float Ey  = Py*ig + 0.5f*ry*q2 + rho*ky;
        float Exx = Pxx*ig + 0.5f*rxx*q2 + 2.f*rx*kx
                  + rho*(ux*ux + u*uxx + wx*wx + w*wxx);
        float Eyy = Pyy*ig + 0.5f*ryy*q2 + 2.f*ry*ky
                  + rho*(uy*uy + u*uyy + wy*wy + w*wyy);

        float f1x = rx*u + rho*ux;
        float f2x = rx*u*u + 2.f*rho*u*ux + Px;
        float f3x = rx*u*w + rho*(ux*w + u*wx);
        float f4x = ux*(E + P) + u*(Ex + Px);

        float g1y = ry*w + rho*wy;
        float g2y = ry*u*w + rho*(uy*w + u*wy);
        float g3y = ry*w*w + 2.f*rho*w*wy + Py;
        float g4y = wy*(E + P) + w*(Ey + Py);

        float Uxx2 = rxx*u + 2.f*rx*ux + rho*uxx;
        float Uyy2 = ryy*u + 2.f*ry*uy + rho*uyy;
        float Uxx3 = rxx*w + 2.f*rx*wx + rho*wxx;
        float Uyy3 = ryy*w + 2.f*ry*wy + rho*wyy;

        float mu = g_mu[p0 + tid];
        float r1 = f1x + g1y - mu*(rxx + ryy);
        float r2 = f2x + g2y - mu*(Uxx2 + Uyy2);
        float r3 = f3x + g3y - mu*(Uxx3 + Uyy3);
        float r4 = f4x + g4y - mu*(Exx + Eyy);
        c = r1*r1 + r2*r2 + r3*r3 + r4*r4;
        sm[1536 + tid] = c;
    }
    __syncthreads();
    if (tid < 32) {
        float vv = sm[1536 + tid] + sm[1536 + tid + 32];
#pragma unroll
        for (int o = 16; o > 0; o >>= 1)
            vv += __shfl_down_sync(0xffffffff, vv, o);
        if (tid == 0) g_phys[blockIdx.x] = vv;
    }
}

// ---------------------------------------------------------------------------
// Boundary kernel: value-only forward pass for 4 sets of 4096 points.
// blockIdx >> 6 selects the set; 64 points per block.
// ---------------------------------------------------------------------------
__global__ void __launch_bounds__(TH, 2)
pinn_bnd_kernel(const float* __restrict__ x_inlet, const float* __restrict__ U_inlet,
                const float* __restrict__ x_base,  const float* __restrict__ x_top,
                const float* __restrict__ x_slip,
                const float* __restrict__ W0, const float* __restrict__ b0,
                const float* __restrict__ W1, const float* __restrict__ b1,
                const float* __restrict__ W2, const float* __restrict__ b2,
                const float* __restrict__ W3, const float* __restrict__ b3,
                const float* __restrict__ W4, const float* __restrict__ b4)
{
    extern __shared__ float sm[];
    const int tid = threadIdx.x;
    const int jg  = tid & 15;
    const int pg  = tid >> 4;
    const int bid = blockIdx.x;
    const int set = bid >> 6;
    const int pbase = (bid & 63) * PTS;

    const float* xp = (set == 0) ? x_inlet : (set == 1) ? x_base
                    : (set == 2) ? x_top   : x_slip;

    float* sW = sm;
    float* sA = sm + OFF_TRK;

    for (int i = tid; i < 512; i += TH) sm[OFF_W4 + i] = W4[i];
    if (tid < 4) sm[OFF_B4 + tid] = b4[tid];

    // input layer (value only)
    {
        float xs[4], ys[4];
#pragma unroll
        for (int i = 0; i < 4; ++i) {
            float2 cc = reinterpret_cast<const float2*>(xp)[pbase + pg*4 + i];
            xs[i] = cc.x; ys[i] = cc.y;
        }
#pragma unroll
        for (int jj = 0; jj < 8; ++jj) {
            int j = jg + 16*jj;
            float w0 = __ldg(W0 + j), w1 = __ldg(W0 + D + j), bb = __ldg(b0 + j);
#pragma unroll
            for (int i = 0; i < 4; ++i)
                sA[j*PTS + pg*4 + i] = tanhf(fmaf(xs[i], w0, fmaf(ys[i], w1, bb)));
        }
    }

    const float* Wl[3] = {W1, W2, W3};
    const float* bl[3] = {b1, b2, b3};

    for (int l = 0; l < 3; ++l) {
        __syncthreads();
        load_weights(sm, Wl[l], bl[l], tid);
        __syncthreads();

        float acc[4][8];
#pragma unroll
        for (int jj = 0; jj < 8; ++jj) {
            float bb = sm[OFF_B + jg + 16*jj];
#pragma unroll
            for (int i = 0; i < 4; ++i) acc[i][jj] = bb;
        }
        gemm_tile(sA, sW, pg, jg, acc);
#pragma unroll
        for (int jj = 0; jj < 8; ++jj)
#pragma unroll
            for (int i = 0; i < 4; ++i) acc[i][jj] = tanhf(acc[i][jj]);
        __syncthreads();
        store_tile(sA, pg, jg, acc);
    }
    __syncthreads();

    // final layer
    const int p = tid & 63;
    const int q = tid >> 6;
    {
        float d = sm[OFF_B4 + q];
#pragma unroll 8
        for (int k = 0; k < D; ++k)
            d = fmaf(sA[k*PTS + p], sm[OFF_W4 + k*4 + q], d);
        sm[q*64 + p] = d;
    }
    __syncthreads();

    float c = 0.f;
    if (tid < 64) {
        float o0 = sm[0*64 + tid], o1 = sm[1*64 + tid];
        float o2 = sm[2*64 + tid], o3 = sm[3*64 + tid];
        if (set == 0) {
            const float* Up = U_inlet + (pbase + tid)*4;
            float d0 = o0 - Up[0], d1 = o1 - Up[1];
            float d2 = o2 - Up[2], d3 = o3 - Up[3];
            c = d0*d0 + d1*d1 + d2*d2 + d3*d3;
        } else if (set == 3) {
            const float sa = -0.17364817766693033f;   // sin(-pi/18)
            const float ca =  0.98480775301220800f;   // cos(-pi/18)
            float t = -o2*sa + o3*ca;
            c = t*t;
        } else {
            c = o3*o3;
        }
        sm[512 + tid] = c;
    }
    __syncthreads();
    if (tid < 32) {
        float vv = sm[512 + tid] + sm[512 + tid + 32];
#pragma unroll
        for (int o = 16; o > 0; o >>= 1)
            vv += __shfl_down_sync(0xffffffff, vv, o);
        if (tid == 0) g_bnd[bid] = vv;
    }
}

// ---------------------------------------------------------------------------
// Viscosity net: mu = 0.01 * mlp2(x)^2 ; also partial sums of mu^2.
// ---------------------------------------------------------------------------
__global__ void __launch_bounds__(256)
mu_kernel(const float* __restrict__ x_train,
          const float* __restrict__ V0, const float* __restrict__ c0,
          const float* __restrict__ V1, const float* __restrict__ c1,
          const float* __restrict__ V2, const float* __restrict__ c2)
{
    __shared__ float sV0[128], sc0[64], sV1[4096], sc1[64], sV2[64], sc2s;
    __shared__ float red[256];
    const int tid = threadIdx.x;

    for (int i = tid; i < 4096; i += 256) sV1[i] = V1[i];
    if (tid < 128) sV0[tid] = V0[tid];
    if (tid < 64) { sc0[tid] = c0[tid]; sc1[tid] = c1[tid]; sV2[tid] = V2[tid]; }
    if (tid == 0) sc2s = c2[0];
    __syncthreads();

    const int p = blockIdx.x * 256 + tid;
    float2 xy = reinterpret_cast<const float2*>(x_train)[p];

    float h1[64];
#pragma unroll
    for (int j = 0; j < 64; ++j)
        h1[j] = tanhf(fmaf(xy.x, sV0[j], fmaf(xy.y, sV0[64 + j], sc0[j])));

    float o = sc2s;
    for (int j = 0; j < 64; ++j) {
        float z = sc1[j];
#pragma unroll
        for (int k = 0; k < 64; ++k) z = fmaf(h1[k], sV1[k*64 + j], z);
        o = fmaf(tanhf(z), sV2[j], o);
    }
    float mu = 0.01f * o * o;
    g_mu[p] = mu;

    red[tid] = mu * mu;
    __syncthreads();
    if (tid < 128) red[tid] += red[tid + 128];
    __syncthreads();
    if (tid < 64) red[tid] += red[tid + 64];
    __syncthreads();
    if (tid < 32) {
        float vv = red[tid] + red[tid + 32];
#pragma unroll
        for (int oo = 16; oo > 0; oo >>= 1)
            vv += __shfl_down_sync(0xffffffff, vv, oo);
        if (tid == 0) g_mu2[blockIdx.x] = vv;
    }
}

// ---------------------------------------------------------------------------
// Final deterministic reduction.
// total = physics/N + 10/NB * sum(bnd) + 0.1/N * sum(mu2)
// ---------------------------------------------------------------------------
__global__ void __launch_bounds__(256)
reduce_kernel(float* __restrict__ out)
{
    __shared__ float red[256];
    const int tid = threadIdx.x;
    float a = (g_phys[tid] + g_phys[tid + 256]) * (1.f / 32768.f);
    a += g_bnd[tid] * (10.f / 4096.f);
    if (tid < 128) a += g_mu2[tid] * (0.1f / 32768.f);
    red[tid] = a;
    __syncthreads();
    if (tid < 128) red[tid] += red[tid + 128];
    __syncthreads();
    if (tid < 64) red[tid] += red[tid + 64];
    __syncthreads();
    if (tid < 32) {
        float vv = red[tid] + red[tid + 32];
#pragma unroll
        for (int o = 16; o > 0; o >>= 1)
            vv += __shfl_down_sync(0xffffffff, vv, o);
        if (tid == 0) out[0] = vv;
    }
}

// ---------------------------------------------------------------------------
extern "C" void kernel_launch(void* const* d_in, const int* in_sizes, int n_in,
                              void* d_out, int out_size)
{
    const float* x_train = (const float*)d_in[0];
    const float* x_inlet = (const float*)d_in[1];
    const float* U_inlet = (const float*)d_in[2];
    const float* x_base  = (const float*)d_in[3];
    const float* x_top   = (const float*)d_in[4];
    const float* x_slip  = (const float*)d_in[5];
    const float* W0 = (const float*)d_in[6];  const float* b0 = (const float*)d_in[7];
    const float* W1 = (const float*)d_in[8];  const float* b1 = (const float*)d_in[9];
    const float* W2 = (const float*)d_in[10]; const float* b2 = (const float*)d_in[11];
    const float* W3 = (const float*)d_in[12]; const float* b3 = (const float*)d_in[13];
    const float* W4 = (const float*)d_in[14]; const float* b4 = (const float*)d_in[15];
    const float* V0 = (const float*)d_in[16]; const float* c0 = (const float*)d_in[17];
    const float* V1 = (const float*)d_in[18]; const float* c1 = (const float*)d_in[19];
    const float* V2 = (const float*)d_in[20]; const float* c2 = (const float*)d_in[21];

    cudaFuncSetAttribute(pinn_main_kernel,
                         cudaFuncAttributeMaxDynamicSharedMemorySize, SM_MAIN);
    cudaFuncSetAttribute(pinn_bnd_kernel,
                         cudaFuncAttributeMaxDynamicSharedMemorySize, SM_BND);

    mu_kernel<<<NTRAIN/256, 256>>>(x_train, V0, c0, V1, c1, V2, c2);
    pinn_main_kernel<<<NTRAIN/PTS, TH, SM_MAIN>>>(x_train,
        W0, b0, W1, b1, W2, b2, W3, b3, W4, b4);
    pinn_bnd_kernel<<<4*(NB/PTS), TH, SM_BND>>>(x_inlet, U_inlet, x_base, x_top,
        x_slip, W0, b0, W1, b1, W2, b2, W3, b3, W4, b4);
    reduce_kernel<<<1, 256>>>((float*)d_out);
}

// round 3
// speedup vs baseline: 1.4014x; 1.4014x over previous
#include <cuda_runtime.h>
#include <math.h>

#define D       128
#define NTRAIN  32768
#define NB      4096

typedef unsigned long long u64;

// shared-memory float offsets (main & bnd share prefix layout)
#define OFF_B    16384          // per-layer bias (128)
#define OFF_W4   16512          // final weights 128x4
#define OFF_B4   17024          // final bias (4)
#define OFF_TRK  17040          // track buffers start
#define TRK_SZ   (D*64)         // 8192 floats per track (64 points)
#define SM_MAIN  ((OFF_TRK + 5*TRK_SZ)*4)   // 232000 B
#define SM_BND   ((OFF_TRK + 1*TRK_SZ)*4)   // 100928 B

#define MTH 512                 // main kernel threads
#define BTH 256                 // boundary kernel threads

// scratch (static device globals — no allocations)
__device__ float g_mu[NTRAIN];
__device__ float g_phys[NTRAIN/64];      // 512
__device__ float g_mu2[NTRAIN/256];      // 128
__device__ float g_bnd[4*(NB/64)];       // 256

// ---------------------------------------------------------------------------
// packed fp32x2 helpers (sm_103a FFMA2 — PTX-only)
// ---------------------------------------------------------------------------
__device__ __forceinline__ u64 pk2(float lo, float hi) {
    u64 r; asm("mov.b64 %0, {%1, %2};" : "=l"(r) : "f"(lo), "f"(hi)); return r;
}
__device__ __forceinline__ void upk2(u64 v, float& lo, float& hi) {
    asm("mov.b64 {%0, %1}, %2;" : "=f"(lo), "=f"(hi) : "l"(v));
}
__device__ __forceinline__ void fma2(u64& d, u64 a, u64 b) {
    asm("fma.rn.f32x2 %0, %1, %2, %0;" : "+l"(d) : "l"(a), "l"(b));
}

// ---------------------------------------------------------------------------
// Main physics kernel. 64 pts/block, 512 threads.
// Thread tile: 2-point packed pair x 8 cols, 5 tracks fused in one k-loop.
// Track layout swizzled at float2 granularity: float2-chunk = pg ^ (row & 31).
// ---------------------------------------------------------------------------
__global__ void __launch_bounds__(MTH, 1)
pinn_main_kernel(const float* __restrict__ x_train,
                 const float* __restrict__ W0, const float* __restrict__ b0,
                 const float* __restrict__ W1, const float* __restrict__ b1,
                 const float* __restrict__ W2, const float* __restrict__ b2,
                 const float* __restrict__ W3, const float* __restrict__ b3,
                 const float* __restrict__ W4, const float* __restrict__ b4)
{
    extern __shared__ float sm[];
    const int tid = threadIdx.x;
    const int jg  = tid & 15;       // column group (16)
    const int pg  = tid >> 4;       // point-pair index (32)
    const int p0  = blockIdx.x * 64;

    float* sW   = sm;
    float* sA   = sm + OFF_TRK;
    float* sAx  = sA   + TRK_SZ;
    float* sAy  = sAx  + TRK_SZ;
    float* sAxx = sAy  + TRK_SZ;
    float* sAyy = sAxx + TRK_SZ;

    // final-layer weights persist whole kernel
    for (int i = tid; i < 512; i += MTH) sm[OFF_W4 + i] = W4[i];
    if (tid < 4) sm[OFF_B4 + tid] = b4[tid];

    // ---- input layer (2 -> 128), closed form, 5 tracks ----
    {
        float2 c0 = reinterpret_cast<const float2*>(x_train)[p0 + pg*2];
        float2 c1 = reinterpret_cast<const float2*>(x_train)[p0 + pg*2 + 1];
#pragma unroll
        for (int jj = 0; jj < 8; ++jj) {
            int j = jg + 16*jj;
            float w0 = __ldg(W0 + j), w1 = __ldg(W0 + D + j), bb = __ldg(b0 + j);
            float z0 = fmaf(c0.x, w0, fmaf(c0.y, w1, bb));
            float z1 = fmaf(c1.x, w0, fmaf(c1.y, w1, bb));
            float a0 = tanhf(z0), a1 = tanhf(z1);
            float s0 = 1.f - a0*a0, s1 = 1.f - a1*a1;
            float q0 = -2.f*a0*s0, q1 = -2.f*a1*s1;
            int fo = j*64 + ((pg ^ (j & 31)) << 1);
            *reinterpret_cast<u64*>(sA  + fo) = pk2(a0, a1);
            *reinterpret_cast<u64*>(sAx + fo) = pk2(s0*w0, s1*w0);
            *reinterpret_cast<u64*>(sAy + fo) = pk2(s0*w1, s1*w1);
            *reinterpret_cast<u64*>(sAxx+ fo) = pk2(q0*w0*w0, q1*w0*w0);
            *reinterpret_cast<u64*>(sAyy+ fo) = pk2(q0*w1*w1, q1*w1*w1);
        }
    }

    const float* Wl[3] = {W1, W2, W3};
    const float* bl[3] = {b1, b2, b3};

    for (int l = 0; l < 3; ++l) {
        __syncthreads();
        {   // load 128x128 weights + bias (512 threads)
            float4* dw = reinterpret_cast<float4*>(sW);
            const float4* sw = reinterpret_cast<const float4*>(Wl[l]);
#pragma unroll
            for (int i = 0; i < 8; ++i) dw[tid + i*MTH] = sw[tid + i*MTH];
            if (tid < 32)
                reinterpret_cast<float4*>(sm + OFF_B)[tid] =
                    reinterpret_cast<const float4*>(bl[l])[tid];
        }
        __syncthreads();

        // ---- fused 5-track GEMM ----
        u64 cv[8], cx[8], cy[8], cxx[8], cyy[8];
#pragma unroll
        for (int jj = 0; jj < 8; ++jj) {
            float bb = sm[OFF_B + jg + 16*jj];
            cv[jj]  = pk2(bb, bb);
            cx[jj] = 0ull; cy[jj] = 0ull; cxx[jj] = 0ull; cyy[jj] = 0ull;
        }
#pragma unroll 2
        for (int k = 0; k < D; ++k) {
            int fo = k*64 + ((pg ^ (k & 31)) << 1);
            u64 av   = *reinterpret_cast<const u64*>(sA   + fo);
            u64 axv  = *reinterpret_cast<const u64*>(sAx  + fo);
            u64 ayv  = *reinterpret_cast<const u64*>(sAy  + fo);
            u64 axxv = *reinterpret_cast<const u64*>(sAxx + fo);
            u64 ayyv = *reinterpret_cast<const u64*>(sAyy + fo);
            const float* wk = sW + k*D + jg;
#pragma unroll
            for (int jj = 0; jj < 8; ++jj) {
                float w = wk[16*jj];
                u64 w2 = pk2(w, w);
                fma2(cv[jj],  av,   w2);
                fma2(cx[jj],  axv,  w2);
                fma2(cy[jj],  ayv,  w2);
                fma2(cxx[jj], axxv, w2);
                fma2(cyy[jj], ayyv, w2);
            }
        }
        __syncthreads();   // all reads of old tracks complete before overwrite

        // ---- register epilogue: tanh chain for both packed points ----
#pragma unroll
        for (int jj = 0; jj < 8; ++jj) {
            int j = jg + 16*jj;
            float zv0, zv1, zx0, zx1, zy0, zy1, zxx0, zxx1, zyy0, zyy1;
            upk2(cv[jj],  zv0,  zv1);
            upk2(cx[jj],  zx0,  zx1);
            upk2(cy[jj],  zy0,  zy1);
            upk2(cxx[jj], zxx0, zxx1);
            upk2(cyy[jj], zyy0, zyy1);
            float a0 = tanhf(zv0), a1 = tanhf(zv1);
            float s0 = 1.f - a0*a0, s1 = 1.f - a1*a1;
            int fo = j*64 + ((pg ^ (j & 31)) << 1);
            *reinterpret_cast<u64*>(sA  + fo) = pk2(a0, a1);
            *reinterpret_cast<u64*>(sAx + fo) = pk2(s0*zx0, s1*zx1);
            *reinterpret_cast<u64*>(sAy + fo) = pk2(s0*zy0, s1*zy1);
            *reinterpret_cast<u64*>(sAxx+ fo) =
                pk2(s0*(zxx0 - 2.f*a0*zx0*zx0), s1*(zxx1 - 2.f*a1*zx1*zx1));
            *reinterpret_cast<u64*>(sAyy+ fo) =
                pk2(s0*(zyy0 - 2.f*a0*zy0*zy0), s1*(zyy1 - 2.f*a1*zy1*zy1));
        }
    }
    __syncthreads();

    // ---- final layer (128 -> 4) for all 5 tracks (threads 0..255) ----
    if (tid < 256) {
        const int p = tid & 63;
        const int q = tid >> 6;
        float val[5];
#pragma unroll
        for (int t = 0; t < 5; ++t) {
            const float* trk = sA + t*TRK_SZ;
            float d = (t == 0) ? sm[OFF_B4 + q] : 0.f;
#pragma unroll 8
            for (int k = 0; k < D; ++k) {
                int fo = k*64 + ((((p >> 1) ^ (k & 31)) << 1) | (p & 1));
                d = fmaf(trk[fo], sm[OFF_W4 + k*4 + q], d);
            }
            val[t] = d;
        }
        __syncthreads();   // tracks fully read; sW region reused for staging
#pragma unroll
        for (int t = 0; t < 5; ++t) sm[(t*4 + q)*64 + p] = val[t];
    } else {
        __syncthreads();
    }
    __syncthreads();

    // ---- Euler flux residual, one thread per point ----
    if (tid < 64) {
        float v[5][4];
#pragma unroll
        for (int t = 0; t < 5; ++t)
#pragma unroll
            for (int qq = 0; qq < 4; ++qq)
                v[t][qq] = sm[(t*4 + qq)*64 + tid];

        float rho = v[0][0], P  = v[0][1], u  = v[0][2], w  = v[0][3];
        float rx  = v[1][0], Px = v[1][1], ux = v[1][2], wx = v[1][3];
        float ry  = v[2][0], Py = v[2][1], uy = v[2][2], wy = v[2][3];
        float rxx = v[3][0], Pxx= v[3][1], uxx= v[3][2], wxx= v[3][3];
        float ryy = v[4][0], Pyy= v[4][1], uyy= v[4][2], wyy= v[4][3];

        const float ig = 2.5f;                 // 1/(gamma-1)
        float q2  = u*u + w*w;
        float kx  = u*ux + w*wx;
        float ky  = u*uy + w*wy;
        float E   = P*ig  + 0.5f*rho*q2;
        float Ex  = Px*ig + 0.5f*rx*q2 + rho*kx;
        float Ey  = Py*ig + 0.5f*ry*q2 + rho*ky;
        float Exx = Pxx*ig + 0.5f*rxx*q2 + 2.f*rx*kx
                  + rho*(ux*ux + u*uxx + wx*wx + w*wxx);
        float Eyy = Pyy*ig + 0.5f*ryy*q2 + 2.f*ry*ky
                  + rho*(uy*uy + u*uyy + wy*wy + w*wyy);

        float f1x = rx*u + rho*ux;
        float f2x = rx*u*u + 2.f*rho*u*ux + Px;
        float f3x = rx*u*w + rho*(ux*w + u*wx);
        float f4x = ux*(E + P) + u*(Ex + Px);

        float g1y = ry*w + rho*wy;
        float g2y = ry*u*w + rho*(uy*w + u*wy);
        float g3y = ry*w*w + 2.f*rho*w*wy + Py;
        float g4y = wy*(E + P) + w*(Ey + Py);

        float Uxx2 = rxx*u + 2.f*rx*ux + rho*uxx;
        float Uyy2 = ryy*u + 2.f*ry*uy + rho*uyy;
        float Uxx3 = rxx*w + 2.f*rx*wx + rho*wxx;
        float Uyy3 = ryy*w + 2.f*ry*wy + rho*wyy;

        float mu = g_mu[p0 + tid];
        float r1 = f1x + g1y - mu*(rxx + ryy);
        float r2 = f2x + g2y - mu*(Uxx2 + Uyy2);
        float r3 = f3x + g3y - mu*(Uxx3 + Uyy3);
        float r4 = f4x + g4y - mu*(Exx + Eyy);
        sm[1536 + tid] = r1*r1 + r2*r2 + r3*r3 + r4*r4;
    }
    __syncthreads();
    if (tid < 32) {
        float vv = sm[1536 + tid] + sm[1536 + tid + 32];
#pragma unroll
        for (int o = 16; o > 0; o >>= 1)
            vv += __shfl_down_sync(0xffffffff, vv, o);
        if (tid == 0) g_phys[blockIdx.x] = vv;
    }
}

// ---------------------------------------------------------------------------
// Boundary kernel: value-only forward pass, 4 sets x 4096 pts, 64 pts/block.
// 256 threads; thread = 2 packed pairs (4 pts) x 8 cols. Swizzle at float4.
// ---------------------------------------------------------------------------
__global__ void __launch_bounds__(BTH, 2)
pinn_bnd_kernel(const float* __restrict__ x_inlet, const float* __restrict__ U_inlet,
                const float* __restrict__ x_base,  const float* __restrict__ x_top,
                const float* __restrict__ x_slip,
                const float* __restrict__ W0, const float* __restrict__ b0,
                const float* __restrict__ W1, const float* __restrict__ b1,
                const float* __restrict__ W2, const float* __restrict__ b2,
                const float* __restrict__ W3, const float* __restrict__ b3,
                const float* __restrict__ W4, const float* __restrict__ b4)
{
    extern __shared__ float sm[];
    const int tid = threadIdx.x;
    const int jg  = tid & 15;
    const int pg  = tid >> 4;          // 0..15, 4 points each
    const int bid = blockIdx.x;
    const int set = bid >> 6;
    const int pbase = (bid & 63) * 64;

    const float* xp = (set == 0) ? x_inlet : (set == 1) ? x_base
                    : (set == 2) ? x_top   : x_slip;

    float* sW = sm;
    float* sA = sm + OFF_TRK;

    for (int i = tid; i < 512; i += BTH) sm[OFF_W4 + i] = W4[i];
    if (tid < 4) sm[OFF_B4 + tid] = b4[tid];

    // input layer (value only)
    {
        float xs[4], ys[4];
#pragma unroll
        for (int i = 0; i < 4; ++i) {
            float2 cc = reinterpret_cast<const float2*>(xp)[pbase + pg*4 + i];
            xs[i] = cc.x; ys[i] = cc.y;
        }
#pragma unroll
        for (int jj = 0; jj < 8; ++jj) {
            int j = jg + 16*jj;
            float w0 = __ldg(W0 + j), w1 = __ldg(W0 + D + j), bb = __ldg(b0 + j);
            float4 st;
            st.x = tanhf(fmaf(xs[0], w0, fmaf(ys[0], w1, bb)));
            st.y = tanhf(fmaf(xs[1], w0, fmaf(ys[1], w1, bb)));
            st.z = tanhf(fmaf(xs[2], w0, fmaf(ys[2], w1, bb)));
            st.w = tanhf(fmaf(xs[3], w0, fmaf(ys[3], w1, bb)));
            *reinterpret_cast<float4*>(sA + j*64 + ((pg ^ (j & 15)) << 2)) = st;
        }
    }

    const float* Wl[3] = {W1, W2, W3};
    const float* bl[3] = {b1, b2, b3};

    for (int l = 0; l < 3; ++l) {
        __syncthreads();
        {
            float4* dw = reinterpret_cast<float4*>(sW);
            const float4* sw = reinterpret_cast<const float4*>(Wl[l]);
#pragma unroll
            for (int i = 0; i < 16; ++i) dw[tid + i*BTH] = sw[tid + i*BTH];
            if (tid < 32)
                reinterpret_cast<float4*>(sm + OFF_B)[tid] =
                    reinterpret_cast<const float4*>(bl[l])[tid];
        }
        __syncthreads();

        u64 c0[8], c1[8];
#pragma unroll
        for (int jj = 0; jj < 8; ++jj) {
            float bb = sm[OFF_B + jg + 16*jj];
            c0[jj] = pk2(bb, bb); c1[jj] = pk2(bb, bb);
        }
#pragma unroll 2
        for (int k = 0; k < D; ++k) {
            ulonglong2 av = *reinterpret_cast<const ulonglong2*>(
                sA + k*64 + ((pg ^ (k & 15)) << 2));
            const float* wk = sW + k*D + jg;
#pragma unroll
            for (int jj = 0; jj < 8; ++jj) {
                float w = wk[16*jj];
                u64 w2 = pk2(w, w);
                fma2(c0[jj], av.x, w2);
                fma2(c1[jj], av.y, w2);
            }
        }
        __syncthreads();
#pragma unroll
        for (int jj = 0; jj < 8; ++jj) {
            int j = jg + 16*jj;
            float z0, z1, z2, z3;
            upk2(c0[jj], z0, z1);
            upk2(c1[jj], z2, z3);
            float4 st = make_float4(tanhf(z0), tanhf(z1), tanhf(z2), tanhf(z3));
            *reinterpret_cast<float4*>(sA + j*64 + ((pg ^ (j & 15)) << 2)) = st;
        }
    }
    __syncthreads();

    // final layer
    const int p = tid & 63;
    const int q = tid >> 6;
    {
        float d = sm[OFF_B4 + q];
#pragma unroll 8
        for (int k = 0; k < D; ++k) {
            int fo = k*64 + (((p >> 2) ^ (k & 15)) << 2) + (p & 3);
            d = fmaf(sA[fo], sm[OFF_W4 + k*4 + q], d);
        }
        __syncthreads();
        sm[q*64 + p] = d;
    }
    __syncthreads();

    if (tid < 64) {
        float o0 = sm[0*64 + tid], o1 = sm[1*64 + tid];
        float o2 = sm[2*64 + tid], o3 = sm[3*64 + tid];
        float c;
        if (set == 0) {
            const float* Up = U_inlet + (pbase + tid)*4;
            float d0 = o0 - Up[0], d1 = o1 - Up[1];
            float d2 = o2 - Up[2], d3 = o3 - Up[3];
            c = d0*d0 + d1*d1 + d2*d2 + d3*d3;
        } else if (set == 3) {
            const float sa = -0.17364817766693033f;   // sin(-pi/18)
            const float ca =  0.98480775301220800f;   // cos(-pi/18)
            float t = -o2*sa + o3*ca;
            c = t*t;
        } else {
            c = o3*o3;
        }
        sm[512 + tid] = c;
    }
    __syncthreads();
    if (tid < 32) {
        float vv = sm[512 + tid] + sm[512 + tid + 32];
#pragma unroll
        for (int o = 16; o > 0; o >>= 1)
            vv += __shfl_down_sync(0xffffffff, vv, o);
        if (tid == 0) g_bnd[bid] = vv;
    }
}

// ---------------------------------------------------------------------------
// Viscosity net: mu = 0.01 * mlp2(x)^2 ; partial sums of mu^2.
// ---------------------------------------------------------------------------
__global__ void __launch_bounds__(256)
mu_kernel(const float* __restrict__ x_train,
          const float* __restrict__ V0, const float* __restrict__ c0,
          const float* __restrict__ V1, const float* __restrict__ c1,
          const float* __restrict__ V2, const float* __restrict__ c2)
{
    __shared__ float sV0[128], sc0[64], sV1[4096], sc1[64], sV2[64], sc2s;
    __shared__ float red[256];
    const int tid = threadIdx.x;

    for (int i = tid; i < 4096; i += 256) sV1[i] = V1[i];
    if (tid < 128) sV0[tid] = V0[tid];
    if (tid < 64) { sc0[tid] = c0[tid]; sc1[tid] = c1[tid]; sV2[tid] = V2[tid]; }
    if (tid == 0) sc2s = c2[0];
    __syncthreads();

    const int p = blockIdx.x * 256 + tid;
    float2 xy = reinterpret_cast<const float2*>(x_train)[p];

    float h1[64];
#pragma unroll
    for (int j = 0; j < 64; ++j)
        h1[j] = tanhf(fmaf(xy.x, sV0[j], fmaf(xy.y, sV0[64 + j], sc0[j])));

    float o = sc2s;
    for (int j = 0; j < 64; ++j) {
        float z = sc1[j];
#pragma unroll
        for (int k = 0; k < 64; ++k) z = fmaf(h1[k], sV1[k*64 + j], z);
        o = fmaf(tanhf(z), sV2[j], o);
    }
    float mu = 0.01f * o * o;
    g_mu[p] = mu;

    red[tid] = mu * mu;
    __syncthreads();
    if (tid < 128) red[tid] += red[tid + 128];
    __syncthreads();
    if (tid < 64) red[tid] += red[tid + 64];
    __syncthreads();
    if (tid < 32) {
        float vv = red[tid] + red[tid + 32];
#pragma unroll
        for (int oo = 16; oo > 0; oo >>= 1)
            vv += __shfl_down_sync(0xffffffff, vv, oo);
        if (tid == 0) g_mu2[blockIdx.x] = vv;
    }
}

// ---------------------------------------------------------------------------
// Final deterministic reduction.
// ---------------------------------------------------------------------------
__global__ void __launch_bounds__(256)
reduce_kernel(float* __restrict__ out)
{
    __shared__ float red[256];
    const int tid = threadIdx.x;
    float a = (g_phys[tid] + g_phys[tid + 256]) * (1.f / 32768.f);
    a += g_bnd[tid] * (10.f / 4096.f);
    if (tid < 128) a += g_mu2[tid] * (0.1f / 32768.f);
    red[tid] = a;
    __syncthreads();
    if (tid < 128) red[tid] += red[tid + 128];
    __syncthreads();
    if (tid < 64) red[tid] += red[tid + 64];
    __syncthreads();
    if (tid < 32) {
        float vv = red[tid] + red[tid + 32];
#pragma unroll
        for (int o = 16; o > 0; o >>= 1)
            vv += __shfl_down_sync(0xffffffff, vv, o);
        if (tid == 0) out[0] = vv;
    }
}

// ---------------------------------------------------------------------------
extern "C" void kernel_launch(void* const* d_in, const int* in_sizes, int n_in,
                              void* d_out, int out_size)
{
    const float* x_train = (const float*)d_in[0];
    const float* x_inlet = (const float*)d_in[1];
    const float* U_inlet = (const float*)d_in[2];
    const float* x_base  = (const float*)d_in[3];
    const float* x_top   = (const float*)d_in[4];
    const float* x_slip  = (const float*)d_in[5];
    const float* W0 = (const float*)d_in[6];  const float* b0 = (const float*)d_in[7];
    const float* W1 = (const float*)d_in[8];  const float* b1 = (const float*)d_in[9];
    const float* W2 = (const float*)d_in[10]; const float* b2 = (const float*)d_in[11];
    const float* W3 = (const float*)d_in[12]; const float* b3 = (const float*)d_in[13];
    const float* W4 = (const float*)d_in[14]; const float* b4 = (const float*)d_in[15];
    const float* V0 = (const float*)d_in[16]; const float* c0 = (const float*)d_in[17];
    const float* V1 = (const float*)d_in[18]; const float* c1 = (const float*)d_in[19];
    const float* V2 = (const float*)d_in[20]; const float* c2 = (const float*)d_in[21];

    cudaFuncSetAttribute(pinn_main_kernel,
                         cudaFuncAttributeMaxDynamicSharedMemorySize, SM_MAIN);
    cudaFuncSetAttribute(pinn_bnd_kernel,
                         cudaFuncAttributeMaxDynamicSharedMemorySize, SM_BND);

    mu_kernel<<<NTRAIN/256, 256>>>(x_train, V0, c0, V1, c1, V2, c2);
    pinn_main_kernel<<<NTRAIN/64, MTH, SM_MAIN>>>(x_train,
        W0, b0, W1, b1, W2, b2, W3, b3, W4, b4);
    pinn_bnd_kernel<<<4*(NB/64), BTH, SM_BND>>>(x_inlet, U_inlet, x_base, x_top,
        x_slip, W0, b0, W1, b1, W2, b2, W3, b3, W4, b4);
    reduce_kernel<<<1, 256>>>((float*)d_out);
}

// round 4
// speedup vs baseline: 1.4618x; 1.0431x over previous
#include <cuda_runtime.h>
#include <math.h>

#define D       128
#define NTRAIN  32768
#define NB      4096

typedef unsigned long long u64;

// shared-memory float offsets
#define OFF_B    16384          // per-layer bias (128)
#define OFF_W4   16512          // final weights 128x4
#define OFF_B4   17024          // final bias (4)
#define OFF_TRK  17040          // track buffers start
#define TRK_SZ   (D*64)         // 8192 floats per track (64 points)
#define SM_MAIN  ((OFF_TRK + 5*TRK_SZ)*4)   // 232000 B

#define MTH 512
#define NMAINBLK (NTRAIN/64)    // 512
#define NBNDBLK  (4*(NB/64))    // 256

// scratch (static device globals — no allocations)
__device__ float g_mu[NTRAIN];
__device__ float g_phys[NMAINBLK];       // 512
__device__ float g_mu2[NTRAIN/256];      // 128
__device__ float g_bnd[NBNDBLK];         // 256

// ---------------------------------------------------------------------------
// packed fp32x2 helpers (sm_103a FFMA2 — PTX-only)
// ---------------------------------------------------------------------------
__device__ __forceinline__ u64 pk2(float lo, float hi) {
    u64 r; asm("mov.b64 %0, {%1, %2};" : "=l"(r) : "f"(lo), "f"(hi)); return r;
}
__device__ __forceinline__ void upk2(u64 v, float& lo, float& hi) {
    asm("mov.b64 {%0, %1}, %2;" : "=f"(lo), "=f"(hi) : "l"(v));
}
__device__ __forceinline__ void fma2(u64& d, u64 a, u64 b) {
    asm("fma.rn.f32x2 %0, %1, %2, %0;" : "+l"(d) : "l"(a), "l"(b));
}

// ---------------------------------------------------------------------------
// Fused kernel. Blocks [0,512): physics (5 tracks). Blocks [512,768): boundary
// (value track only). 64 pts/block, 512 threads, occ 1 (232 KB smem).
// Track layout swizzled at float2 granularity: chunk = pg ^ (row & 31).
// ---------------------------------------------------------------------------
__global__ void __launch_bounds__(MTH, 1)
pinn_fused_kernel(const float* __restrict__ x_train,
                  const float* __restrict__ x_inlet, const float* __restrict__ U_inlet,
                  const float* __restrict__ x_base,  const float* __restrict__ x_top,
                  const float* __restrict__ x_slip,
                  const float* __restrict__ W0, const float* __restrict__ b0,
                  const float* __restrict__ W1, const float* __restrict__ b1,
                  const float* __restrict__ W2, const float* __restrict__ b2,
                  const float* __restrict__ W3, const float* __restrict__ b3,
                  const float* __restrict__ W4, const float* __restrict__ b4)
{
    extern __shared__ float sm[];
    const int tid = threadIdx.x;
    const int jg  = tid & 15;       // column group (16)
    const int pg  = tid >> 4;       // point-pair index (32)

    float* sW   = sm;
    float* sA   = sm + OFF_TRK;
    float* sAx  = sA   + TRK_SZ;
    float* sAy  = sAx  + TRK_SZ;
    float* sAxx = sAy  + TRK_SZ;
    float* sAyy = sAxx + TRK_SZ;

    const float* Wl[3] = {W1, W2, W3};
    const float* bl[3] = {b1, b2, b3};

    // final-layer weights persist whole kernel
    for (int i = tid; i < 512; i += MTH) sm[OFF_W4 + i] = W4[i];
    if (tid < 4) sm[OFF_B4 + tid] = b4[tid];

    if (blockIdx.x < NMAINBLK) {
        // ===================== PHYSICS PATH =====================
        const int p0 = blockIdx.x * 64;

        // ---- input layer (2 -> 128), closed form, 5 tracks ----
        {
            float2 c0 = reinterpret_cast<const float2*>(x_train)[p0 + pg*2];
            float2 c1 = reinterpret_cast<const float2*>(x_train)[p0 + pg*2 + 1];
#pragma unroll
            for (int jj = 0; jj < 8; ++jj) {
                int j = jg + 16*jj;
                float w0 = __ldg(W0 + j), w1 = __ldg(W0 + D + j), bb = __ldg(b0 + j);
                float z0 = fmaf(c0.x, w0, fmaf(c0.y, w1, bb));
                float z1 = fmaf(c1.x, w0, fmaf(c1.y, w1, bb));
                float a0 = tanhf(z0), a1 = tanhf(z1);
                float s0 = 1.f - a0*a0, s1 = 1.f - a1*a1;
                float q0 = -2.f*a0*s0, q1 = -2.f*a1*s1;
                int fo = j*64 + ((pg ^ (j & 31)) << 1);
                *reinterpret_cast<u64*>(sA  + fo) = pk2(a0, a1);
                *reinterpret_cast<u64*>(sAx + fo) = pk2(s0*w0, s1*w0);
                *reinterpret_cast<u64*>(sAy + fo) = pk2(s0*w1, s1*w1);
                *reinterpret_cast<u64*>(sAxx+ fo) = pk2(q0*w0*w0, q1*w0*w0);
                *reinterpret_cast<u64*>(sAyy+ fo) = pk2(q0*w1*w1, q1*w1*w1);
            }
        }

        for (int l = 0; l < 3; ++l) {
            __syncthreads();
            {   // load 128x128 weights + bias
                float4* dw = reinterpret_cast<float4*>(sW);
                const float4* sw = reinterpret_cast<const float4*>(Wl[l]);
#pragma unroll
                for (int i = 0; i < 8; ++i) dw[tid + i*MTH] = sw[tid + i*MTH];
                if (tid < 32)
                    reinterpret_cast<float4*>(sm + OFF_B)[tid] =
                        reinterpret_cast<const float4*>(bl[l])[tid];
            }
            __syncthreads();

            // ---- fused 5-track GEMM (minimal register liveness) ----
            u64 cv[8], cx[8], cy[8], cxx[8], cyy[8];
#pragma unroll
            for (int jj = 0; jj < 8; ++jj) {
                float bb = sm[OFF_B + jg + 16*jj];
                cv[jj]  = pk2(bb, bb);
                cx[jj] = 0ull; cy[jj] = 0ull; cxx[jj] = 0ull; cyy[jj] = 0ull;
            }
#pragma unroll 1
            for (int k = 0; k < D; ++k) {
                int fo = k*64 + ((pg ^ (k & 31)) << 1);
                u64 av   = *reinterpret_cast<const u64*>(sA   + fo);
                u64 axv  = *reinterpret_cast<const u64*>(sAx  + fo);
                u64 ayv  = *reinterpret_cast<const u64*>(sAy  + fo);
                u64 axxv = *reinterpret_cast<const u64*>(sAxx + fo);
                u64 ayyv = *reinterpret_cast<const u64*>(sAyy + fo);
                const float* wk = sW + k*D + jg;
#pragma unroll
                for (int jj = 0; jj < 8; ++jj) {
                    float w = wk[16*jj];
                    u64 w2 = pk2(w, w);
                    fma2(cv[jj],  av,   w2);
                    fma2(cx[jj],  axv,  w2);
                    fma2(cy[jj],  ayv,  w2);
                    fma2(cxx[jj], axxv, w2);
                    fma2(cyy[jj], ayyv, w2);
                }
            }
            __syncthreads();   // all reads done before overwrite

            // ---- register epilogue: tanh chain for both packed points ----
#pragma unroll
            for (int jj = 0; jj < 8; ++jj) {
                int j = jg + 16*jj;
                float zv0, zv1, zx0, zx1, zy0, zy1, zxx0, zxx1, zyy0, zyy1;
                upk2(cv[jj],  zv0,  zv1);
                upk2(cx[jj],  zx0,  zx1);
                upk2(cy[jj],  zy0,  zy1);
                upk2(cxx[jj], zxx0, zxx1);
                upk2(cyy[jj], zyy0, zyy1);
                float a0 = tanhf(zv0), a1 = tanhf(zv1);
                float s0 = 1.f - a0*a0, s1 = 1.f - a1*a1;
                int fo = j*64 + ((pg ^ (j & 31)) << 1);
                *reinterpret_cast<u64*>(sA  + fo) = pk2(a0, a1);
                *reinterpret_cast<u64*>(sAx + fo) = pk2(s0*zx0, s1*zx1);
                *reinterpret_cast<u64*>(sAy + fo) = pk2(s0*zy0, s1*zy1);
                *reinterpret_cast<u64*>(sAxx+ fo) =
                    pk2(s0*(zxx0 - 2.f*a0*zx0*zx0), s1*(zxx1 - 2.f*a1*zx1*zx1));
                *reinterpret_cast<u64*>(sAyy+ fo) =
                    pk2(s0*(zyy0 - 2.f*a0*zy0*zy0), s1*(zyy1 - 2.f*a1*zy1*zy1));
            }
        }
        __syncthreads();

        // ---- final layer (128 -> 4) for all 5 tracks ----
        if (tid < 256) {
            const int p = tid & 63;
            const int q = tid >> 6;
            float val[5];
#pragma unroll
            for (int t = 0; t < 5; ++t) {
                const float* trk = sA + t*TRK_SZ;
                float d = (t == 0) ? sm[OFF_B4 + q] : 0.f;
#pragma unroll 8
                for (int k = 0; k < D; ++k) {
                    int fo = k*64 + ((((p >> 1) ^ (k & 31)) << 1) | (p & 1));
                    d = fmaf(trk[fo], sm[OFF_W4 + k*4 + q], d);
                }
                val[t] = d;
            }
            __syncthreads();
#pragma unroll
            for (int t = 0; t < 5; ++t) sm[(t*4 + q)*64 + p] = val[t];
        } else {
            __syncthreads();
        }
        __syncthreads();

        // ---- Euler flux residual, one thread per point ----
        if (tid < 64) {
            float v[5][4];
#pragma unroll
            for (int t = 0; t < 5; ++t)
#pragma unroll
                for (int qq = 0; qq < 4; ++qq)
                    v[t][qq] = sm[(t*4 + qq)*64 + tid];

            float rho = v[0][0], P  = v[0][1], u  = v[0][2], w  = v[0][3];
            float rx  = v[1][0], Px = v[1][1], ux = v[1][2], wx = v[1][3];
            float ry  = v[2][0], Py = v[2][1], uy = v[2][2], wy = v[2][3];
            float rxx = v[3][0], Pxx= v[3][1], uxx= v[3][2], wxx= v[3][3];
            float ryy = v[4][0], Pyy= v[4][1], uyy= v[4][2], wyy= v[4][3];

            const float ig = 2.5f;                 // 1/(gamma-1)
            float q2  = u*u + w*w;
            float kx  = u*ux + w*wx;
            float ky  = u*uy + w*wy;
            float E   = P*ig  + 0.5f*rho*q2;
            float Ex  = Px*ig + 0.5f*rx*q2 + rho*kx;
            float Ey  = Py*ig + 0.5f*ry*q2 + rho*ky;
            float Exx = Pxx*ig + 0.5f*rxx*q2 + 2.f*rx*kx
                      + rho*(ux*ux + u*uxx + wx*wx + w*wxx);
            float Eyy = Pyy*ig + 0.5f*ryy*q2 + 2.f*ry*ky
                      + rho*(uy*uy + u*uyy + wy*wy + w*wyy);

            float f1x = rx*u + rho*ux;
            float f2x = rx*u*u + 2.f*rho*u*ux + Px;
            float f3x = rx*u*w + rho*(ux*w + u*wx);
            float f4x = ux*(E + P) + u*(Ex + Px);

            float g1y = ry*w + rho*wy;
            float g2y = ry*u*w + rho*(uy*w + u*wy);
            float g3y = ry*w*w + 2.f*rho*w*wy + Py;
            float g4y = wy*(E + P) + w*(Ey + Py);

            float Uxx2 = rxx*u + 2.f*rx*ux + rho*uxx;
            float Uyy2 = ryy*u + 2.f*ry*uy + rho*uyy;
            float Uxx3 = rxx*w + 2.f*rx*wx + rho*wxx;
            float Uyy3 = ryy*w + 2.f*ry*wy + rho*wyy;

            float mu = g_mu[p0 + tid];
            float r1 = f1x + g1y - mu*(rxx + ryy);
            float r2 = f2x + g2y - mu*(Uxx2 + Uyy2);
            float r3 = f3x + g3y - mu*(Uxx3 + Uyy3);
            float r4 = f4x + g4y - mu*(Exx + Eyy);
            sm[1536 + tid] = r1*r1 + r2*r2 + r3*r3 + r4*r4;
        }
        __syncthreads();
        if (tid < 32) {
            float vv = sm[1536 + tid] + sm[1536 + tid + 32];
#pragma unroll
            for (int o = 16; o > 0; o >>= 1)
                vv += __shfl_down_sync(0xffffffff, vv, o);
            if (tid == 0) g_phys[blockIdx.x] = vv;
        }
    } else {
        // ===================== BOUNDARY PATH =====================
        const int b2 = blockIdx.x - NMAINBLK;        // 0..255
        const int set = b2 >> 6;
        const int pbase = (b2 & 63) * 64;
        const float* xp = (set == 0) ? x_inlet : (set == 1) ? x_base
                        : (set == 2) ? x_top   : x_slip;

        // input layer (value only)
        {
            float2 c0 = reinterpret_cast<const float2*>(xp)[pbase + pg*2];
            float2 c1 = reinterpret_cast<const float2*>(xp)[pbase + pg*2 + 1];
#pragma unroll
            for (int jj = 0; jj < 8; ++jj) {
                int j = jg + 16*jj;
                float w0 = __ldg(W0 + j), w1 = __ldg(W0 + D + j), bb = __ldg(b0 + j);
                float a0 = tanhf(fmaf(c0.x, w0, fmaf(c0.y, w1, bb)));
                float a1 = tanhf(fmaf(c1.x, w0, fmaf(c1.y, w1, bb)));
                *reinterpret_cast<u64*>(sA + j*64 + ((pg ^ (j & 31)) << 1)) = pk2(a0, a1);
            }
        }

        for (int l = 0; l < 3; ++l) {
            __syncthreads();
            {
                float4* dw = reinterpret_cast<float4*>(sW);
                const float4* sw = reinterpret_cast<const float4*>(Wl[l]);
#pragma unroll
                for (int i = 0; i < 8; ++i) dw[tid + i*MTH] = sw[tid + i*MTH];
                if (tid < 32)
                    reinterpret_cast<float4*>(sm + OFF_B)[tid] =
                        reinterpret_cast<const float4*>(bl[l])[tid];
            }
            __syncthreads();

            u64 cv[8];
#pragma unroll
            for (int jj = 0; jj < 8; ++jj) {
                float bb = sm[OFF_B + jg + 16*jj];
                cv[jj] = pk2(bb, bb);
            }
#pragma unroll 2
            for (int k = 0; k < D; ++k) {
                u64 av = *reinterpret_cast<const u64*>(
                    sA + k*64 + ((pg ^ (k & 31)) << 1));
                const float* wk = sW + k*D + jg;
#pragma unroll
                for (int jj = 0; jj < 8; ++jj) {
                    float w = wk[16*jj];
                    fma2(cv[jj], av, pk2(w, w));
                }
            }
            __syncthreads();
#pragma unroll
            for (int jj = 0; jj < 8; ++jj) {
                int j = jg + 16*jj;
                float z0, z1;
                upk2(cv[jj], z0, z1);
                *reinterpret_cast<u64*>(sA + j*64 + ((pg ^ (j & 31)) << 1)) =
                    pk2(tanhf(z0), tanhf(z1));
            }
        }
        __syncthreads();

        // final layer (value only)
        if (tid < 256) {
            const int p = tid & 63;
            const int q = tid >> 6;
            float d = sm[OFF_B4 + q];
#pragma unroll 8
            for (int k = 0; k < D; ++k) {
                int fo = k*64 + ((((p >> 1) ^ (k & 31)) << 1) | (p & 1));
                d = fmaf(sA[fo], sm[OFF_W4 + k*4 + q], d);
            }
            __syncthreads();
            sm[q*64 + p] = d;
        } else {
            __syncthreads();
        }
        __syncthreads();

        if (tid < 64) {
            float o0 = sm[0*64 + tid], o1 = sm[1*64 + tid];
            float o2 = sm[2*64 + tid], o3 = sm[3*64 + tid];
            float c;
            if (set == 0) {
                const float* Up = U_inlet + (pbase + tid)*4;
                float d0 = o0 - Up[0], d1 = o1 - Up[1];
                float d2 = o2 - Up[2], d3 = o3 - Up[3];
                c = d0*d0 + d1*d1 + d2*d2 + d3*d3;
            } else if (set == 3) {
                const float sa = -0.17364817766693033f;   // sin(-pi/18)
                const float ca =  0.98480775301220800f;   // cos(-pi/18)
                float t = -o2*sa + o3*ca;
                c = t*t;
            } else {
                c = o3*o3;
            }
            sm[1536 + tid] = c;
        }
        __syncthreads();
        if (tid < 32) {
            float vv = sm[1536 + tid] + sm[1536 + tid + 32];
#pragma unroll
            for (int o = 16; o > 0; o >>= 1)
                vv += __shfl_down_sync(0xffffffff, vv, o);
            if (tid == 0) g_bnd[b2] = vv;
        }
    }
}

// ---------------------------------------------------------------------------
// Viscosity net: mu = 0.01 * mlp2(x)^2 ; partial sums of mu^2.
// ---------------------------------------------------------------------------
__global__ void __launch_bounds__(256)
mu_kernel(const float* __restrict__ x_train,
          const float* __restrict__ V0, const float* __restrict__ c0,
          const float* __restrict__ V1, const float* __restrict__ c1,
          const float* __restrict__ V2, const float* __restrict__ c2)
{
    __shared__ float sV0[128], sc0[64], sV1[4096], sc1[64], sV2[64], sc2s;
    __shared__ float red[256];
    const int tid = threadIdx.x;

    for (int i = tid; i < 4096; i += 256) sV1[i] = V1[i];
    if (tid < 128) sV0[tid] = V0[tid];
    if (tid < 64) { sc0[tid] = c0[tid]; sc1[tid] = c1[tid]; sV2[tid] = V2[tid]; }
    if (tid == 0) sc2s = c2[0];
    __syncthreads();

    const int p = blockIdx.x * 256 + tid;
    float2 xy = reinterpret_cast<const float2*>(x_train)[p];

    float h1[64];
#pragma unroll
    for (int j = 0; j < 64; ++j)
        h1[j] = tanhf(fmaf(xy.x, sV0[j], fmaf(xy.y, sV0[64 + j], sc0[j])));

    float o = sc2s;
    for (int j = 0; j < 64; ++j) {
        float z = sc1[j];
#pragma unroll
        for (int k = 0; k < 64; ++k) z = fmaf(h1[k], sV1[k*64 + j], z);
        o = fmaf(tanhf(z), sV2[j], o);
    }
    float mu = 0.01f * o * o;
    g_mu[p] = mu;

    red[tid] = mu * mu;
    __syncthreads();
    if (tid < 128) red[tid] += red[tid + 128];
    __syncthreads();
    if (tid < 64) red[tid] += red[tid + 64];
    __syncthreads();
    if (tid < 32) {
        float vv = red[tid] + red[tid + 32];
#pragma unroll
        for (int oo = 16; oo > 0; oo >>= 1)
            vv += __shfl_down_sync(0xffffffff, vv, oo);
        if (tid == 0) g_mu2[blockIdx.x] = vv;
    }
}

// ---------------------------------------------------------------------------
// Final deterministic reduction.
// ---------------------------------------------------------------------------
__global__ void __launch_bounds__(256)
reduce_kernel(float* __restrict__ out)
{
    __shared__ float red[256];
    const int tid = threadIdx.x;
    float a = (g_phys[tid] + g_phys[tid + 256]) * (1.f / 32768.f);
    a += g_bnd[tid] * (10.f / 4096.f);
    if (tid < 128) a += g_mu2[tid] * (0.1f / 32768.f);
    red[tid] = a;
    __syncthreads();
    if (tid < 128) red[tid] += red[tid + 128];
    __syncthreads();
    if (tid < 64) red[tid] += red[tid + 64];
    __syncthreads();
    if (tid < 32) {
        float vv = red[tid] + red[tid + 32];
#pragma unroll
        for (int o = 16; o > 0; o >>= 1)
            vv += __shfl_down_sync(0xffffffff, vv, o);
        if (tid == 0) out[0] = vv;
    }
}

// ---------------------------------------------------------------------------
extern "C" void kernel_launch(void* const* d_in, const int* in_sizes, int n_in,
                              void* d_out, int out_size)
{
    const float* x_train = (const float*)d_in[0];
    const float* x_inlet = (const float*)d_in[1];
    const float* U_inlet = (const float*)d_in[2];
    const float* x_base  = (const float*)d_in[3];
    const float* x_top   = (const float*)d_in[4];
    const float* x_slip  = (const float*)d_in[5];
    const float* W0 = (const float*)d_in[6];  const float* b0 = (const float*)d_in[7];
    const float* W1 = (const float*)d_in[8];  const float* b1 = (const float*)d_in[9];
    const float* W2 = (const float*)d_in[10]; const float* b2 = (const float*)d_in[11];
    const float* W3 = (const float*)d_in[12]; const float* b3 = (const float*)d_in[13];
    const float* W4 = (const float*)d_in[14]; const float* b4 = (const float*)d_in[15];
    const float* V0 = (const float*)d_in[16]; const float* c0 = (const float*)d_in[17];
    const float* V1 = (const float*)d_in[18]; const float* c1 = (const float*)d_in[19];
    const float* V2 = (const float*)d_in[20]; const float* c2 = (const float*)d_in[21];

    cudaFuncSetAttribute(pinn_fused_kernel,
                         cudaFuncAttributeMaxDynamicSharedMemorySize, SM_MAIN);

    mu_kernel<<<NTRAIN/256, 256>>>(x_train, V0, c0, V1, c1, V2, c2);
    pinn_fused_kernel<<<NMAINBLK + NBNDBLK, MTH, SM_MAIN>>>(x_train,
        x_inlet, U_inlet, x_base, x_top, x_slip,
        W0, b0, W1, b1, W2, b2, W3, b3, W4, b4);
    reduce_kernel<<<1, 256>>>((float*)d_out);
}